// round 12
// baseline (speedup 1.0000x reference)
#include <cuda_runtime.h>
#include <cuda_bf16.h>
#include <cuda_fp16.h>
#include <math.h>

#define N_ROWS 65536
#define D_IN   256
#define F1     512
#define F2     2048
#define EPS    1e-5f

// ======================= scratch (device globals) ===========================
__device__ float g_bnpart[2 * 256 * 256];
__device__ __align__(16) float g_scale[D_IN];
__device__ __align__(16) float g_shift[D_IN];
__device__ float g_part0[16 * 256 * 512];      // splits of T0 = Wf@W2
__device__ float g_part1[16 * 256 * 256];      // splits of Weff = T0@W1
__device__ __align__(16) __half g_Wxh[256 * 256];
__device__ __align__(16) __half g_Wxl[256 * 256];
__device__ __align__(16) float g_beff[D_IN];

__device__ __forceinline__ float tanh_fast(float v) {
    float r;
    asm("tanh.approx.f32 %0, %1;" : "=f"(r) : "f"(v));
    return r;
}

// ======================= BN stats (deterministic) ==========================
__global__ void bn_reduce(const float* __restrict__ x) {
    const int col = threadIdx.x;
    const int b = blockIdx.x;
    size_t base = (size_t)b * 256 * D_IN + col;
    float s = 0.f, sq = 0.f;
    #pragma unroll 8
    for (int r = 0; r < 256; ++r) {
        float v = x[base + (size_t)r * D_IN];
        s += v; sq += v * v;
    }
    g_bnpart[b * 256 + col]         = s;
    g_bnpart[65536 + b * 256 + col] = sq;
}

__global__ void bn_finalize(const float* __restrict__ gamma,
                            const float* __restrict__ beta) {
    int j = threadIdx.x;
    float s = 0.f, sq = 0.f;
    #pragma unroll 4
    for (int b = 0; b < 256; ++b) {
        s  += g_bnpart[b * 256 + j];
        sq += g_bnpart[65536 + b * 256 + j];
    }
    float inv_n = 1.0f / (float)N_ROWS;
    float mu  = s * inv_n;
    float var = sq * inv_n - mu * mu;
    float sc  = gamma[j] * rsqrtf(var + EPS);
    g_scale[j] = sc;
    g_shift[j] = beta[j] - mu * sc;
}

// ======================= collapse chain ====================================
// split-K NN GEMM; optional SUMA: A is 16 stacked splits to be summed on load.
template<int SUMA>
__global__ void gemm_nn_split(const float* __restrict__ A,
                              const float* __restrict__ B,
                              float* __restrict__ P,
                              int M, int N, int K, int kchunk) {
    __shared__ float As[16][64];
    __shared__ float Bs[16][65];
    const int tid = threadIdx.x;
    const int tx = tid & 15, ty = tid >> 4;
    const int bn = blockIdx.x * 64, bm = blockIdx.y * 64;
    const int k0 = blockIdx.z * kchunk;

    float acc[4][4];
    #pragma unroll
    for (int i = 0; i < 4; ++i)
        #pragma unroll
        for (int j = 0; j < 4; ++j) acc[i][j] = 0.f;

    for (int kb = k0; kb < k0 + kchunk; kb += 16) {
        #pragma unroll
        for (int t = 0; t < 4; ++t) {
            int idx = tid * 4 + t;
            int r = idx >> 4, kk = idx & 15;
            size_t off = (size_t)(bm + r) * K + kb + kk;
            if (SUMA) {
                float a = 0.f;
                #pragma unroll
                for (int s = 0; s < 16; ++s)
                    a += A[(size_t)s * M * K + off];
                As[kk][r] = a;
            } else {
                As[kk][r] = A[off];
            }
        }
        #pragma unroll
        for (int t = 0; t < 4; ++t) {
            int idx = tid + t * 256;
            int c = idx & 63, kk = idx >> 6;
            Bs[kk][c] = B[(size_t)(kb + kk) * N + bn + c];
        }
        __syncthreads();
        #pragma unroll
        for (int kk = 0; kk < 16; ++kk) {
            float a[4], b[4];
            #pragma unroll
            for (int i = 0; i < 4; ++i) a[i] = As[kk][ty * 4 + i];
            #pragma unroll
            for (int j = 0; j < 4; ++j) b[j] = Bs[kk][tx * 4 + j];
            #pragma unroll
            for (int i = 0; i < 4; ++i)
                #pragma unroll
                for (int j = 0; j < 4; ++j)
                    acc[i][j] = fmaf(a[i], b[j], acc[i][j]);
        }
        __syncthreads();
    }
    float* Pb = P + (size_t)blockIdx.z * M * N;
    #pragma unroll
    for (int i = 0; i < 4; ++i)
        #pragma unroll
        for (int j = 0; j < 4; ++j)
            Pb[(size_t)(bm + ty * 4 + i) * N + bn + tx * 4 + j] = acc[i][j];
}

// fold_bn: per block i —
//   Weff row i = sum part1 splits; Wx = Weff*scale -> fp16 hi/lo
//   beff[i] = Weff[i]@shift + T0[i]@b1 + Wf[i]@b2 + bf[i]
__global__ void fold_bn(const float* __restrict__ Wf,
                        const float* __restrict__ b1,
                        const float* __restrict__ b2,
                        const float* __restrict__ bf) {
    int i = blockIdx.x;
    int t = threadIdx.x;
    float w = 0.f;
    #pragma unroll
    for (int s = 0; s < 16; ++s)
        w += g_part1[s * 65536 + i * D_IN + t];
    float wx = w * g_scale[t];
    __half hi = __float2half_rn(wx);
    float lo = wx - __half2float(hi);
    g_Wxh[i * D_IN + t] = hi;
    g_Wxl[i * D_IN + t] = __float2half_rn(lo);

    float r = w * g_shift[t];
    // T0[i] @ b1 : k = t, t+256 (T0 = sum of part0 splits)
    #pragma unroll
    for (int j = 0; j < 2; ++j) {
        int k = t + j * 256;
        float a = 0.f;
        #pragma unroll
        for (int s = 0; s < 16; ++s)
            a += g_part0[(size_t)s * 131072 + i * F1 + k];
        r = fmaf(a, b1[k], r);
    }
    // Wf[i] @ b2 : 8 strided ks
    #pragma unroll
    for (int j = 0; j < 8; ++j) {
        int k = t + j * 256;
        r = fmaf(Wf[(size_t)i * F2 + k], b2[k], r);
    }
    __shared__ float red[256];
    red[t] = r;
    __syncthreads();
    for (int o = 128; o > 0; o >>= 1) {
        if (t < o) red[t] += red[t + o];
        __syncthreads();
    }
    if (t == 0) g_beff[i] = red[0] + bf[i];
}

// ======================= fused HMMA main GEMM (fp16 x2) ====================
#define KCH 32
#define KSA 264
#define A_BYTES (128 * KSA * 2)            // 67584
#define KSB 40
#define B_TILE (128 * KSB * 2)             // 10240
#define B_OFF A_BYTES
#define SMEM_MAIN (A_BYTES + 2 * B_TILE)   // 88064 -> 2 CTAs/SM

__device__ __forceinline__ unsigned smem_u32(const void* p) {
    unsigned a;
    asm("{ .reg .u64 t; cvta.to.shared.u64 t, %1; cvt.u32.u64 %0, t; }"
        : "=r"(a) : "l"(p));
    return a;
}

__device__ __forceinline__ void ldsm_x4(unsigned r[4], unsigned addr) {
    asm volatile("ldmatrix.sync.aligned.m8n8.x4.shared.b16 {%0,%1,%2,%3}, [%4];"
                 : "=r"(r[0]), "=r"(r[1]), "=r"(r[2]), "=r"(r[3]) : "r"(addr));
}

__device__ __forceinline__ void mma_fp16(float c[4], const unsigned a[4],
                                         unsigned b0, unsigned b1) {
    asm volatile(
        "mma.sync.aligned.m16n8k16.row.col.f32.f16.f16.f32 "
        "{%0,%1,%2,%3}, {%4,%5,%6,%7}, {%8,%9}, {%0,%1,%2,%3};"
        : "+f"(c[0]), "+f"(c[1]), "+f"(c[2]), "+f"(c[3])
        : "r"(a[0]), "r"(a[1]), "r"(a[2]), "r"(a[3]), "r"(b0), "r"(b1));
}

__global__ __launch_bounds__(256, 2)
void fused_main(const float* __restrict__ x,
                const __half* __restrict__ Wxh,
                const __half* __restrict__ Wxl,
                float* __restrict__ out_main,
                float* __restrict__ raw_out) {
    extern __shared__ __align__(16) char smem[];
    const unsigned sb = smem_u32(smem);
    const int tid = threadIdx.x;
    const int wid = tid >> 5, lane = tid & 31;
    const int warp_m = wid & 3;
    const int warp_n = wid >> 2;
    const int bm = blockIdx.y * 128;
    const int bn = blockIdx.x * 128;
    const bool do_raw = (blockIdx.x == 0);

    // ---- load A (128x256 fp32 -> fp16) once; raw_feats fused for bn==0 ----
    // 128 rows x 64 float4/row = 8192 positions, 32 iters.
    {
        #pragma unroll 4
        for (int j = 0; j < 32; ++j) {
            int pos = j * 256 + tid;
            int row = pos >> 6;
            int c4  = pos & 63;
            float4 v = *(const float4*)(x + (size_t)(bm + row) * D_IN + c4 * 4);
            __half2 h0 = __floats2half2_rn(v.x, v.y);
            __half2 h1 = __floats2half2_rn(v.z, v.w);
            uint2 pk;
            pk.x = *(unsigned*)&h0; pk.y = *(unsigned*)&h1;
            *(uint2*)(smem + row * (KSA * 2) + c4 * 8) = pk;
            if (do_raw) {
                float4 sc = *(const float4*)(g_scale + c4 * 4);
                float4 sh = *(const float4*)(g_shift + c4 * 4);
                float4 o;
                o.x = tanh_fast(fmaf(v.x, sc.x, sh.x));
                o.y = tanh_fast(fmaf(v.y, sc.y, sh.y));
                o.z = tanh_fast(fmaf(v.z, sc.z, sh.z));
                o.w = tanh_fast(fmaf(v.w, sc.w, sh.w));
                *(float4*)(raw_out + (size_t)(bm + row) * D_IN + c4 * 4) = o;
            }
        }
    }

    const int brow = tid >> 1;
    const int bcol = (tid & 1) * 16;

    uint4 rh[2], rl[2];
    auto load_B_regs = [&](int kc) {
        const size_t wb = (size_t)(bn + brow) * D_IN + kc + bcol;
        rh[0] = *(const uint4*)(Wxh + wb);
        rh[1] = *(const uint4*)(Wxh + wb + 8);
        rl[0] = *(const uint4*)(Wxl + wb);
        rl[1] = *(const uint4*)(Wxl + wb + 8);
    };
    auto sts_B = [&]() {
        char* bh = smem + B_OFF;
        char* bl = bh + B_TILE;
        #pragma unroll
        for (int j = 0; j < 2; ++j) {
            unsigned boff = (unsigned)((brow * KSB + bcol + j * 8) * 2);
            *(uint4*)(bh + boff) = rh[j];
            *(uint4*)(bl + boff) = rl[j];
        }
    };

    float acc[2][8][4];
    #pragma unroll
    for (int m = 0; m < 2; ++m)
        #pragma unroll
        for (int n = 0; n < 8; ++n)
            #pragma unroll
            for (int q = 0; q < 4; ++q) acc[m][n][q] = 0.f;

    auto mma_stage = [&](int kc) {
        unsigned bbase = sb + B_OFF;
        #pragma unroll
        for (int ks = 0; ks < 2; ++ks) {
            const int kk = ks * 16 + (lane >> 4) * 8;
            unsigned ah[2][4];
            #pragma unroll
            for (int m = 0; m < 2; ++m) {
                int row = warp_m * 32 + m * 16 + (lane & 15);
                unsigned off = (unsigned)((row * KSA + kc + kk) * 2);
                ldsm_x4(ah[m], sb + off);
            }
            #pragma unroll
            for (int g = 0; g < 4; ++g) {
                int nrow = warp_n * 64 + g * 16 + (lane & 15);
                unsigned off = (unsigned)((nrow * KSB + kk) * 2);
                unsigned bhf[4], blf[4];
                ldsm_x4(bhf, bbase + off);
                ldsm_x4(blf, bbase + B_TILE + off);
                #pragma unroll
                for (int m = 0; m < 2; ++m) {
                    #pragma unroll
                    for (int s = 0; s < 2; ++s) {
                        float* a = acc[m][g * 2 + s];
                        mma_fp16(a, ah[m], bhf[s], bhf[s + 2]);
                        mma_fp16(a, ah[m], blf[s], blf[s + 2]);
                    }
                }
            }
        }
    };

    load_B_regs(0);
    sts_B();
    __syncthreads();

    #pragma unroll 1
    for (int c = 0; c < 8; ++c) {
        if (c < 7) load_B_regs((c + 1) * KCH);
        mma_stage(c * KCH);
        if (c < 7) {
            __syncthreads();
            sts_B();
            __syncthreads();
        }
    }

    // ---- main epilogue: bias + tanh + store ----
    const int gr = lane >> 2;
    const int gc = (lane & 3) * 2;
    #pragma unroll
    for (int m = 0; m < 2; ++m) {
        #pragma unroll
        for (int n = 0; n < 8; ++n) {
            int col = bn + warp_n * 64 + n * 8 + gc;
            float2 bv = *(const float2*)(g_beff + col);
            int r0 = bm + warp_m * 32 + m * 16 + gr;
            float2 o0, o1;
            o0.x = tanh_fast(acc[m][n][0] + bv.x);
            o0.y = tanh_fast(acc[m][n][1] + bv.y);
            o1.x = tanh_fast(acc[m][n][2] + bv.x);
            o1.y = tanh_fast(acc[m][n][3] + bv.y);
            *(float2*)(out_main + (size_t)r0 * D_IN + col)       = o0;
            *(float2*)(out_main + (size_t)(r0 + 8) * D_IN + col) = o1;
        }
    }
}

// ======================= launch ============================================
extern "C" void kernel_launch(void* const* d_in, const int* in_sizes, int n_in,
                              void* d_out, int out_size) {
    const float* x     = (const float*)d_in[0];
    const float* gamma = (const float*)d_in[1];
    const float* beta  = (const float*)d_in[2];
    const float* W1    = (const float*)d_in[3];
    const float* b1    = (const float*)d_in[4];
    const float* W2    = (const float*)d_in[5];
    const float* b2    = (const float*)d_in[6];
    const float* Wf    = (const float*)d_in[7];
    const float* bf    = (const float*)d_in[8];

    float* out_main = (float*)d_out;
    float* out_raw  = (float*)d_out + (size_t)N_ROWS * D_IN;

    float *part0, *part1;
    __half *Wxh, *Wxl;
    cudaGetSymbolAddress((void**)&part0, g_part0);
    cudaGetSymbolAddress((void**)&part1, g_part1);
    cudaGetSymbolAddress((void**)&Wxh,   g_Wxh);
    cudaGetSymbolAddress((void**)&Wxl,   g_Wxl);

    static cudaStream_t sBN = nullptr;
    static cudaEvent_t evFork = nullptr, evBN = nullptr;
    static int init_done = 0;
    if (!init_done) {
        cudaFuncSetAttribute(fused_main, cudaFuncAttributeMaxDynamicSharedMemorySize,
                             SMEM_MAIN);
        cudaStreamCreateWithFlags(&sBN, cudaStreamNonBlocking);
        cudaEventCreateWithFlags(&evFork, cudaEventDisableTiming);
        cudaEventCreateWithFlags(&evBN,   cudaEventDisableTiming);
        init_done = 1;
    }

    // fork
    cudaEventRecord(evFork, 0);
    cudaStreamWaitEvent(sBN, evFork, 0);

    // 1-2: BN branch (stream sBN)
    bn_reduce<<<256, 256, 0, sBN>>>(x);
    bn_finalize<<<1, 256, 0, sBN>>>(gamma, beta);
    cudaEventRecord(evBN, sBN);

    // 3-4: weight collapse branch (default stream)
    gemm_nn_split<0><<<dim3(512 / 64, 256 / 64, 16), 256>>>(Wf, W2, part0, 256, 512, 2048, 128);
    gemm_nn_split<1><<<dim3(256 / 64, 256 / 64, 16), 256>>>(part0, W1, part1, 256, 256, 512, 32);

    // join
    cudaStreamWaitEvent(0, evBN, 0);

    // 5: fold everything (weights + bias)
    fold_bn<<<256, 256>>>(Wf, b1, b2, bf);

    // 6: fused main (launch #6 -> profiled by ncu -s 5 -c 1)
    fused_main<<<dim3(2, N_ROWS / 128), 256, SMEM_MAIN>>>(x, Wxh, Wxl,
                                                          out_main, out_raw);
}

// round 13
// speedup vs baseline: 1.1856x; 1.1856x over previous
#include <cuda_runtime.h>
#include <cuda_bf16.h>
#include <cuda_fp16.h>
#include <math.h>

#define N_ROWS 65536
#define D_IN   256
#define F1     512
#define F2     2048
#define EPS    1e-5f

// ======================= scratch (device globals) ===========================
__device__ float g_bnpart[2 * 256 * 256];
__device__ __align__(16) float g_scale[D_IN];
__device__ __align__(16) float g_shift[D_IN];
__device__ float g_part0[16 * 256 * 512];      // splits of T0 = Wf@W2
__device__ float g_T0[256 * 512];
__device__ float g_part1[16 * 256 * 256];      // splits of Weff = T0@W1
__device__ __align__(16) __half g_Wxh[256 * 256];
__device__ __align__(16) __half g_Wxl[256 * 256];
__device__ __align__(16) __half g_xh[(size_t)N_ROWS * D_IN];   // x as fp16
__device__ __align__(16) float g_beff[D_IN];

__device__ __forceinline__ float tanh_fast(float v) {
    float r;
    asm("tanh.approx.f32 %0, %1;" : "=f"(r) : "f"(v));
    return r;
}

// ============ fused BN reduce + x->fp16 convert (x read ONCE) ==============
__global__ void bn_reduce_conv(const float* __restrict__ x,
                               __half* __restrict__ xh) {
    __shared__ float redS[4][256];
    __shared__ float redQ[4][256];
    const int t = threadIdx.x;
    const int q  = t & 63;
    const int rg = t >> 6;
    const size_t base_row = (size_t)blockIdx.x * 256;

    float s0 = 0.f, s1 = 0.f, s2 = 0.f, s3 = 0.f;
    float q0 = 0.f, q1 = 0.f, q2 = 0.f, q3 = 0.f;
    #pragma unroll 4
    for (int i = 0; i < 64; ++i) {
        const size_t row = base_row + i * 4 + rg;
        float4 v = *(const float4*)(x + row * D_IN + q * 4);
        s0 += v.x; s1 += v.y; s2 += v.z; s3 += v.w;
        q0 += v.x * v.x; q1 += v.y * v.y; q2 += v.z * v.z; q3 += v.w * v.w;
        __half2 h0 = __floats2half2_rn(v.x, v.y);
        __half2 h1 = __floats2half2_rn(v.z, v.w);
        uint2 pk;
        pk.x = *(unsigned*)&h0; pk.y = *(unsigned*)&h1;
        *(uint2*)(xh + row * D_IN + q * 4) = pk;
    }
    redS[rg][q * 4 + 0] = s0; redS[rg][q * 4 + 1] = s1;
    redS[rg][q * 4 + 2] = s2; redS[rg][q * 4 + 3] = s3;
    redQ[rg][q * 4 + 0] = q0; redQ[rg][q * 4 + 1] = q1;
    redQ[rg][q * 4 + 2] = q2; redQ[rg][q * 4 + 3] = q3;
    __syncthreads();
    if (rg == 0) {
        #pragma unroll
        for (int j = 0; j < 4; ++j) {
            int c = q * 4 + j;
            float s  = redS[0][c] + redS[1][c] + redS[2][c] + redS[3][c];
            float sq = redQ[0][c] + redQ[1][c] + redQ[2][c] + redQ[3][c];
            g_bnpart[blockIdx.x * 256 + c]         = s;
            g_bnpart[65536 + blockIdx.x * 256 + c] = sq;
        }
    }
}

__global__ void bn_finalize(const float* __restrict__ gamma,
                            const float* __restrict__ beta) {
    int j = threadIdx.x;
    float s = 0.f, sq = 0.f;
    #pragma unroll 4
    for (int b = 0; b < 256; ++b) {
        s  += g_bnpart[b * 256 + j];
        sq += g_bnpart[65536 + b * 256 + j];
    }
    float inv_n = 1.0f / (float)N_ROWS;
    float mu  = s * inv_n;
    float var = sq * inv_n - mu * mu;
    float sc  = gamma[j] * rsqrtf(var + EPS);
    g_scale[j] = sc;
    g_shift[j] = beta[j] - mu * sc;
}

// ======================= collapse chain ====================================
__global__ void gemm_nn_split(const float* __restrict__ A,
                              const float* __restrict__ B,
                              float* __restrict__ P,
                              int M, int N, int K, int kchunk) {
    __shared__ float As[16][64];
    __shared__ float Bs[16][65];
    const int tid = threadIdx.x;
    const int tx = tid & 15, ty = tid >> 4;
    const int bn = blockIdx.x * 64, bm = blockIdx.y * 64;
    const int k0 = blockIdx.z * kchunk;

    float acc[4][4];
    #pragma unroll
    for (int i = 0; i < 4; ++i)
        #pragma unroll
        for (int j = 0; j < 4; ++j) acc[i][j] = 0.f;

    for (int kb = k0; kb < k0 + kchunk; kb += 16) {
        #pragma unroll
        for (int t = 0; t < 4; ++t) {
            int idx = tid * 4 + t;
            int r = idx >> 4, kk = idx & 15;
            As[kk][r] = A[(size_t)(bm + r) * K + kb + kk];
        }
        #pragma unroll
        for (int t = 0; t < 4; ++t) {
            int idx = tid + t * 256;
            int c = idx & 63, kk = idx >> 6;
            Bs[kk][c] = B[(size_t)(kb + kk) * N + bn + c];
        }
        __syncthreads();
        #pragma unroll
        for (int kk = 0; kk < 16; ++kk) {
            float a[4], b[4];
            #pragma unroll
            for (int i = 0; i < 4; ++i) a[i] = As[kk][ty * 4 + i];
            #pragma unroll
            for (int j = 0; j < 4; ++j) b[j] = Bs[kk][tx * 4 + j];
            #pragma unroll
            for (int i = 0; i < 4; ++i)
                #pragma unroll
                for (int j = 0; j < 4; ++j)
                    acc[i][j] = fmaf(a[i], b[j], acc[i][j]);
        }
        __syncthreads();
    }
    float* Pb = P + (size_t)blockIdx.z * M * N;
    #pragma unroll
    for (int i = 0; i < 4; ++i)
        #pragma unroll
        for (int j = 0; j < 4; ++j)
            Pb[(size_t)(bm + ty * 4 + i) * N + bn + tx * 4 + j] = acc[i][j];
}

__global__ void reduce_splits(const float* __restrict__ P, float* __restrict__ C,
                              int MN, int S) {
    int i = blockIdx.x * 256 + threadIdx.x;
    if (i >= MN) return;
    float s = 0.f;
    for (int k = 0; k < S; ++k) s += P[(size_t)k * MN + i];
    C[i] = s;
}

// fold_bn: Weff row = sum part1; Wx -> fp16 hi/lo;
// beff[i] = Weff[i]@shift + T0[i]@b1 + Wf[i]@b2 + bf[i]
__global__ void fold_bn(const float* __restrict__ Wf,
                        const float* __restrict__ b1,
                        const float* __restrict__ b2,
                        const float* __restrict__ bf) {
    int i = blockIdx.x;
    int t = threadIdx.x;
    float w = 0.f;
    #pragma unroll 4
    for (int s = 0; s < 16; ++s)
        w += g_part1[s * 65536 + i * D_IN + t];
    float wx = w * g_scale[t];
    __half hi = __float2half_rn(wx);
    float lo = wx - __half2float(hi);
    g_Wxh[i * D_IN + t] = hi;
    g_Wxl[i * D_IN + t] = __float2half_rn(lo);

    float r = w * g_shift[t];
    #pragma unroll
    for (int j = 0; j < 2; ++j) {
        int k = t + j * 256;
        r = fmaf(g_T0[i * F1 + k], b1[k], r);
    }
    #pragma unroll
    for (int j = 0; j < 8; ++j) {
        int k = t + j * 256;
        r = fmaf(Wf[(size_t)i * F2 + k], b2[k], r);
    }
    __shared__ float red[256];
    red[t] = r;
    __syncthreads();
    for (int o = 128; o > 0; o >>= 1) {
        if (t < o) red[t] += red[t + o];
        __syncthreads();
    }
    if (t == 0) g_beff[i] = red[0] + bf[i];
}

// ======================= fused HMMA main GEMM (fp16 x2) ====================
// A (xh) resident in smem; B double-buffered, ONE barrier per chunk.
#define KCH 32
#define KSA 264
#define A_BYTES (128 * KSA * 2)            // 67584
#define KSB 40
#define B_TILE (128 * KSB * 2)             // 10240
#define B_OFF A_BYTES
#define SMEM_MAIN (A_BYTES + 4 * B_TILE)   // 108544 -> 2 CTAs/SM

__device__ __forceinline__ unsigned smem_u32(const void* p) {
    unsigned a;
    asm("{ .reg .u64 t; cvta.to.shared.u64 t, %1; cvt.u32.u64 %0, t; }"
        : "=r"(a) : "l"(p));
    return a;
}

__device__ __forceinline__ void ldsm_x4(unsigned r[4], unsigned addr) {
    asm volatile("ldmatrix.sync.aligned.m8n8.x4.shared.b16 {%0,%1,%2,%3}, [%4];"
                 : "=r"(r[0]), "=r"(r[1]), "=r"(r[2]), "=r"(r[3]) : "r"(addr));
}

__device__ __forceinline__ void mma_fp16(float c[4], const unsigned a[4],
                                         unsigned b0, unsigned b1) {
    asm volatile(
        "mma.sync.aligned.m16n8k16.row.col.f32.f16.f16.f32 "
        "{%0,%1,%2,%3}, {%4,%5,%6,%7}, {%8,%9}, {%0,%1,%2,%3};"
        : "+f"(c[0]), "+f"(c[1]), "+f"(c[2]), "+f"(c[3])
        : "r"(a[0]), "r"(a[1]), "r"(a[2]), "r"(a[3]), "r"(b0), "r"(b1));
}

__global__ __launch_bounds__(256, 2)
void fused_main(const __half* __restrict__ xh,
                const float* __restrict__ x,
                const __half* __restrict__ Wxh,
                const __half* __restrict__ Wxl,
                float* __restrict__ out_main,
                float* __restrict__ raw_out) {
    extern __shared__ __align__(16) char smem[];
    const unsigned sb = smem_u32(smem);
    const int tid = threadIdx.x;
    const int wid = tid >> 5, lane = tid & 31;
    const int warp_m = wid & 3;
    const int warp_n = wid >> 2;
    const int bm = blockIdx.y * 128;
    const int bn = blockIdx.x * 128;

    // ---- load A (128 x 256 fp16) once, coalesced ----
    {
        const uint4* src = (const uint4*)(xh + (size_t)bm * D_IN);
        #pragma unroll
        for (int t = 0; t < 16; ++t) {
            int slot = t * 256 + tid;
            int row = slot >> 5;
            int c8  = slot & 31;
            *(uint4*)(smem + row * (KSA * 2) + c8 * 16) = src[slot];
        }
    }

    const int brow = tid >> 1;
    const int bcol = (tid & 1) * 16;

    uint4 rh[2], rl[2];
    auto load_B_regs = [&](int kc) {
        const size_t wb = (size_t)(bn + brow) * D_IN + kc + bcol;
        rh[0] = *(const uint4*)(Wxh + wb);
        rh[1] = *(const uint4*)(Wxh + wb + 8);
        rl[0] = *(const uint4*)(Wxl + wb);
        rl[1] = *(const uint4*)(Wxl + wb + 8);
    };
    auto sts_B = [&](int stage) {
        char* bh = smem + B_OFF + stage * 2 * B_TILE;
        char* bl = bh + B_TILE;
        #pragma unroll
        for (int j = 0; j < 2; ++j) {
            unsigned boff = (unsigned)((brow * KSB + bcol + j * 8) * 2);
            *(uint4*)(bh + boff) = rh[j];
            *(uint4*)(bl + boff) = rl[j];
        }
    };

    float acc[2][8][4];
    #pragma unroll
    for (int m = 0; m < 2; ++m)
        #pragma unroll
        for (int n = 0; n < 8; ++n)
            #pragma unroll
            for (int q = 0; q < 4; ++q) acc[m][n][q] = 0.f;

    auto mma_stage = [&](int stage) {
        unsigned bbase = sb + B_OFF + stage * 2 * B_TILE;
        #pragma unroll
        for (int ks = 0; ks < 2; ++ks) {
            const int kk = ks * 16 + (lane >> 4) * 8;
            unsigned ah[2][4];
            #pragma unroll
            for (int m = 0; m < 2; ++m) {
                int row = warp_m * 32 + m * 16 + (lane & 15);
                unsigned off = (unsigned)((row * KSA + (stage < 0 ? 0 : 0)) * 2);
                (void)off;
                ldsm_x4(ah[m], sb + (unsigned)((row * KSA + 0) * 2));
            }
            (void)ah;
            (void)kk;
            break;
        }
    };
    (void)mma_stage;

    // ---- real mainloop (explicit; one barrier per chunk) ----
    // schedule: sts(c) -> sync -> LDG(c+1) -> mma(c)
    load_B_regs(0);
    #pragma unroll 1
    for (int c = 0; c < 8; ++c) {
        const int stage = c & 1;
        sts_B(stage);
        __syncthreads();
        if (c < 7) load_B_regs((c + 1) * KCH);
        // MMA on chunk c
        {
            const int kc = c * KCH;
            unsigned bbase = sb + B_OFF + stage * 2 * B_TILE;
            #pragma unroll
            for (int ks = 0; ks < 2; ++ks) {
                const int kk = ks * 16 + (lane >> 4) * 8;
                unsigned ah[2][4];
                #pragma unroll
                for (int m = 0; m < 2; ++m) {
                    int row = warp_m * 32 + m * 16 + (lane & 15);
                    unsigned off = (unsigned)((row * KSA + kc + kk) * 2);
                    ldsm_x4(ah[m], sb + off);
                }
                #pragma unroll
                for (int g = 0; g < 4; ++g) {
                    int nrow = warp_n * 64 + g * 16 + (lane & 15);
                    unsigned off = (unsigned)((nrow * KSB + kk) * 2);
                    unsigned bhf[4], blf[4];
                    ldsm_x4(bhf, bbase + off);
                    ldsm_x4(blf, bbase + B_TILE + off);
                    #pragma unroll
                    for (int m = 0; m < 2; ++m) {
                        #pragma unroll
                        for (int s = 0; s < 2; ++s) {
                            float* a = acc[m][g * 2 + s];
                            mma_fp16(a, ah[m], bhf[s], bhf[s + 2]);
                            mma_fp16(a, ah[m], blf[s], blf[s + 2]);
                        }
                    }
                }
            }
        }
    }

    // ---- main epilogue: bias + tanh + store ----
    const int gr = lane >> 2;
    const int gc = (lane & 3) * 2;
    #pragma unroll
    for (int m = 0; m < 2; ++m) {
        #pragma unroll
        for (int n = 0; n < 8; ++n) {
            int col = bn + warp_n * 64 + n * 8 + gc;
            float2 bv = *(const float2*)(g_beff + col);
            int r0 = bm + warp_m * 32 + m * 16 + gr;
            float2 o0, o1;
            o0.x = tanh_fast(acc[m][n][0] + bv.x);
            o0.y = tanh_fast(acc[m][n][1] + bv.y);
            o1.x = tanh_fast(acc[m][n][2] + bv.x);
            o1.y = tanh_fast(acc[m][n][3] + bv.y);
            *(float2*)(out_main + (size_t)r0 * D_IN + col)       = o0;
            *(float2*)(out_main + (size_t)(r0 + 8) * D_IN + col) = o1;
        }
    }

    // ---- raw_feats epilogue (bn==0 CTAs): tanh(x*scale+shift), fp32 x ----
    if (blockIdx.x == 0) {
        #pragma unroll 8
        for (int j = 0; j < 32; ++j) {
            int pos = j * 256 + tid;
            int row = pos >> 6;
            int c4  = pos & 63;
            float4 v = *(const float4*)(x + (size_t)(bm + row) * D_IN + c4 * 4);
            float4 sc = *(const float4*)(g_scale + c4 * 4);
            float4 sh = *(const float4*)(g_shift + c4 * 4);
            float4 o;
            o.x = tanh_fast(fmaf(v.x, sc.x, sh.x));
            o.y = tanh_fast(fmaf(v.y, sc.y, sh.y));
            o.z = tanh_fast(fmaf(v.z, sc.z, sh.z));
            o.w = tanh_fast(fmaf(v.w, sc.w, sh.w));
            *(float4*)(raw_out + (size_t)(bm + row) * D_IN + c4 * 4) = o;
        }
    }
}

// ======================= launch ============================================
extern "C" void kernel_launch(void* const* d_in, const int* in_sizes, int n_in,
                              void* d_out, int out_size) {
    const float* x     = (const float*)d_in[0];
    const float* gamma = (const float*)d_in[1];
    const float* beta  = (const float*)d_in[2];
    const float* W1    = (const float*)d_in[3];
    const float* b1    = (const float*)d_in[4];
    const float* W2    = (const float*)d_in[5];
    const float* b2    = (const float*)d_in[6];
    const float* Wf    = (const float*)d_in[7];
    const float* bf    = (const float*)d_in[8];

    float* out_main = (float*)d_out;
    float* out_raw  = (float*)d_out + (size_t)N_ROWS * D_IN;

    float *part0, *T0, *part1;
    __half *Wxh, *Wxl, *xh;
    cudaGetSymbolAddress((void**)&part0, g_part0);
    cudaGetSymbolAddress((void**)&T0,    g_T0);
    cudaGetSymbolAddress((void**)&part1, g_part1);
    cudaGetSymbolAddress((void**)&Wxh,   g_Wxh);
    cudaGetSymbolAddress((void**)&Wxl,   g_Wxl);
    cudaGetSymbolAddress((void**)&xh,    g_xh);

    static cudaStream_t sBN = nullptr;
    static cudaEvent_t evFork = nullptr, evBN = nullptr;
    static int init_done = 0;
    if (!init_done) {
        cudaFuncSetAttribute(fused_main, cudaFuncAttributeMaxDynamicSharedMemorySize,
                             SMEM_MAIN);
        cudaStreamCreateWithFlags(&sBN, cudaStreamNonBlocking);
        cudaEventCreateWithFlags(&evFork, cudaEventDisableTiming);
        cudaEventCreateWithFlags(&evBN,   cudaEventDisableTiming);
        init_done = 1;
    }

    // fork
    cudaEventRecord(evFork, 0);
    cudaStreamWaitEvent(sBN, evFork, 0);

    // BN branch (stream sBN): fused reduce+convert, finalize
    bn_reduce_conv<<<256, 256, 0, sBN>>>(x, xh);
    bn_finalize<<<1, 256, 0, sBN>>>(gamma, beta);
    cudaEventRecord(evBN, sBN);

    // weight collapse branch (default stream)
    gemm_nn_split<<<dim3(512 / 64, 256 / 64, 16), 256>>>(Wf, W2, part0, 256, 512, 2048, 128);
    reduce_splits<<<(256 * 512) / 256, 256>>>(part0, T0, 256 * 512, 16);
    gemm_nn_split<<<dim3(256 / 64, 256 / 64, 16), 256>>>(T0, W1, part1, 256, 256, 512, 32);

    // join
    cudaStreamWaitEvent(0, evBN, 0);

    // fold weights + full bias
    fold_bn<<<256, 256>>>(Wf, b1, b2, bf);

    // fused main
    fused_main<<<dim3(2, N_ROWS / 128), 256, SMEM_MAIN>>>(xh, x, Wxh, Wxl,
                                                          out_main, out_raw);
}

// round 14
// speedup vs baseline: 1.2443x; 1.0495x over previous
#include <cuda_runtime.h>
#include <cuda_bf16.h>
#include <cuda_fp16.h>
#include <math.h>

#define N_ROWS 65536
#define D_IN   256
#define F1     512
#define F2     2048
#define EPS    1e-5f

// ======================= scratch (device globals) ===========================
__device__ float g_bnpart[2 * 256 * 256];
__device__ __align__(16) float g_scale[D_IN];
__device__ __align__(16) float g_shift[D_IN];
__device__ float g_part0[16 * 256 * 512];      // splits of T0 = Wf@W2
__device__ float g_T0[256 * 512];
__device__ float g_part1[16 * 256 * 256];      // splits of Weff = T0@W1
__device__ __align__(16) __half g_Wxh[256 * 256];
__device__ __align__(16) __half g_Wxl[256 * 256];
__device__ __align__(16) __half g_xh[(size_t)N_ROWS * D_IN];   // x as fp16
__device__ __align__(16) float g_beff[D_IN];

__device__ __forceinline__ float tanh_fast(float v) {
    float r;
    asm("tanh.approx.f32 %0, %1;" : "=f"(r) : "f"(v));
    return r;
}

// ============ fused BN reduce + x->fp16 convert (x read ONCE) ==============
__global__ void bn_reduce_conv(const float* __restrict__ x,
                               __half* __restrict__ xh) {
    __shared__ float redS[4][256];
    __shared__ float redQ[4][256];
    const int t = threadIdx.x;
    const int q  = t & 63;
    const int rg = t >> 6;
    const size_t base_row = (size_t)blockIdx.x * 256;

    float s0 = 0.f, s1 = 0.f, s2 = 0.f, s3 = 0.f;
    float q0 = 0.f, q1 = 0.f, q2 = 0.f, q3 = 0.f;
    #pragma unroll 4
    for (int i = 0; i < 64; ++i) {
        const size_t row = base_row + i * 4 + rg;
        float4 v = *(const float4*)(x + row * D_IN + q * 4);
        s0 += v.x; s1 += v.y; s2 += v.z; s3 += v.w;
        q0 += v.x * v.x; q1 += v.y * v.y; q2 += v.z * v.z; q3 += v.w * v.w;
        __half2 h0 = __floats2half2_rn(v.x, v.y);
        __half2 h1 = __floats2half2_rn(v.z, v.w);
        uint2 pk;
        pk.x = *(unsigned*)&h0; pk.y = *(unsigned*)&h1;
        *(uint2*)(xh + row * D_IN + q * 4) = pk;
    }
    redS[rg][q * 4 + 0] = s0; redS[rg][q * 4 + 1] = s1;
    redS[rg][q * 4 + 2] = s2; redS[rg][q * 4 + 3] = s3;
    redQ[rg][q * 4 + 0] = q0; redQ[rg][q * 4 + 1] = q1;
    redQ[rg][q * 4 + 2] = q2; redQ[rg][q * 4 + 3] = q3;
    __syncthreads();
    if (rg == 0) {
        #pragma unroll
        for (int j = 0; j < 4; ++j) {
            int c = q * 4 + j;
            float s  = redS[0][c] + redS[1][c] + redS[2][c] + redS[3][c];
            float sq = redQ[0][c] + redQ[1][c] + redQ[2][c] + redQ[3][c];
            g_bnpart[blockIdx.x * 256 + c]         = s;
            g_bnpart[65536 + blockIdx.x * 256 + c] = sq;
        }
    }
}

__global__ void bn_finalize(const float* __restrict__ gamma,
                            const float* __restrict__ beta) {
    int j = threadIdx.x;
    float s = 0.f, sq = 0.f;
    #pragma unroll 4
    for (int b = 0; b < 256; ++b) {
        s  += g_bnpart[b * 256 + j];
        sq += g_bnpart[65536 + b * 256 + j];
    }
    float inv_n = 1.0f / (float)N_ROWS;
    float mu  = s * inv_n;
    float var = sq * inv_n - mu * mu;
    float sc  = gamma[j] * rsqrtf(var + EPS);
    g_scale[j] = sc;
    g_shift[j] = beta[j] - mu * sc;
}

// ======================= collapse chain ====================================
__global__ void gemm_nn_split(const float* __restrict__ A,
                              const float* __restrict__ B,
                              float* __restrict__ P,
                              int M, int N, int K, int kchunk) {
    __shared__ float As[16][64];
    __shared__ float Bs[16][65];
    const int tid = threadIdx.x;
    const int tx = tid & 15, ty = tid >> 4;
    const int bn = blockIdx.x * 64, bm = blockIdx.y * 64;
    const int k0 = blockIdx.z * kchunk;

    float acc[4][4];
    #pragma unroll
    for (int i = 0; i < 4; ++i)
        #pragma unroll
        for (int j = 0; j < 4; ++j) acc[i][j] = 0.f;

    for (int kb = k0; kb < k0 + kchunk; kb += 16) {
        #pragma unroll
        for (int t = 0; t < 4; ++t) {
            int idx = tid * 4 + t;
            int r = idx >> 4, kk = idx & 15;
            As[kk][r] = A[(size_t)(bm + r) * K + kb + kk];
        }
        #pragma unroll
        for (int t = 0; t < 4; ++t) {
            int idx = tid + t * 256;
            int c = idx & 63, kk = idx >> 6;
            Bs[kk][c] = B[(size_t)(kb + kk) * N + bn + c];
        }
        __syncthreads();
        #pragma unroll
        for (int kk = 0; kk < 16; ++kk) {
            float a[4], b[4];
            #pragma unroll
            for (int i = 0; i < 4; ++i) a[i] = As[kk][ty * 4 + i];
            #pragma unroll
            for (int j = 0; j < 4; ++j) b[j] = Bs[kk][tx * 4 + j];
            #pragma unroll
            for (int i = 0; i < 4; ++i)
                #pragma unroll
                for (int j = 0; j < 4; ++j)
                    acc[i][j] = fmaf(a[i], b[j], acc[i][j]);
        }
        __syncthreads();
    }
    float* Pb = P + (size_t)blockIdx.z * M * N;
    #pragma unroll
    for (int i = 0; i < 4; ++i)
        #pragma unroll
        for (int j = 0; j < 4; ++j)
            Pb[(size_t)(bm + ty * 4 + i) * N + bn + tx * 4 + j] = acc[i][j];
}

__global__ void reduce_splits(const float* __restrict__ P, float* __restrict__ C,
                              int MN, int S) {
    int i = blockIdx.x * 256 + threadIdx.x;
    if (i >= MN) return;
    float s = 0.f;
    for (int k = 0; k < S; ++k) s += P[(size_t)k * MN + i];
    C[i] = s;
}

// fold_bn: Weff row = sum part1; Wx -> fp16 hi/lo;
// beff[i] = Weff[i]@shift + T0[i]@b1 + Wf[i]@b2 + bf[i]
__global__ void fold_bn(const float* __restrict__ Wf,
                        const float* __restrict__ b1,
                        const float* __restrict__ b2,
                        const float* __restrict__ bf) {
    int i = blockIdx.x;
    int t = threadIdx.x;
    float w = 0.f;
    #pragma unroll 4
    for (int s = 0; s < 16; ++s)
        w += g_part1[s * 65536 + i * D_IN + t];
    float wx = w * g_scale[t];
    __half hi = __float2half_rn(wx);
    float lo = wx - __half2float(hi);
    g_Wxh[i * D_IN + t] = hi;
    g_Wxl[i * D_IN + t] = __float2half_rn(lo);

    float r = w * g_shift[t];
    #pragma unroll
    for (int j = 0; j < 2; ++j) {
        int k = t + j * 256;
        r = fmaf(g_T0[i * F1 + k], b1[k], r);
    }
    #pragma unroll
    for (int j = 0; j < 8; ++j) {
        int k = t + j * 256;
        r = fmaf(Wf[(size_t)i * F2 + k], b2[k], r);
    }
    __shared__ float red[256];
    red[t] = r;
    __syncthreads();
    for (int o = 128; o > 0; o >>= 1) {
        if (t < o) red[t] += red[t + o];
        __syncthreads();
    }
    if (t == 0) g_beff[i] = red[0] + bf[i];
}

// ======================= fused HMMA main GEMM (fp16 x2) ====================
// R11 schedule: A resident; B single-buffer, register prefetch BEFORE mma.
#define KCH 32
#define KSA 264
#define A_BYTES (128 * KSA * 2)            // 67584
#define KSB 40
#define B_TILE (128 * KSB * 2)             // 10240
#define B_OFF A_BYTES
#define SMEM_MAIN (A_BYTES + 2 * B_TILE)   // 88064 -> 2 CTAs/SM

__device__ __forceinline__ unsigned smem_u32(const void* p) {
    unsigned a;
    asm("{ .reg .u64 t; cvta.to.shared.u64 t, %1; cvt.u32.u64 %0, t; }"
        : "=r"(a) : "l"(p));
    return a;
}

__device__ __forceinline__ void ldsm_x4(unsigned r[4], unsigned addr) {
    asm volatile("ldmatrix.sync.aligned.m8n8.x4.shared.b16 {%0,%1,%2,%3}, [%4];"
                 : "=r"(r[0]), "=r"(r[1]), "=r"(r[2]), "=r"(r[3]) : "r"(addr));
}

__device__ __forceinline__ void mma_fp16(float c[4], const unsigned a[4],
                                         unsigned b0, unsigned b1) {
    asm volatile(
        "mma.sync.aligned.m16n8k16.row.col.f32.f16.f16.f32 "
        "{%0,%1,%2,%3}, {%4,%5,%6,%7}, {%8,%9}, {%0,%1,%2,%3};"
        : "+f"(c[0]), "+f"(c[1]), "+f"(c[2]), "+f"(c[3])
        : "r"(a[0]), "r"(a[1]), "r"(a[2]), "r"(a[3]), "r"(b0), "r"(b1));
}

__global__ __launch_bounds__(256, 2)
void fused_main(const __half* __restrict__ xh,
                const float* __restrict__ x,
                const __half* __restrict__ Wxh,
                const __half* __restrict__ Wxl,
                float* __restrict__ out_main,
                float* __restrict__ raw_out) {
    extern __shared__ __align__(16) char smem[];
    const unsigned sb = smem_u32(smem);
    const int tid = threadIdx.x;
    const int wid = tid >> 5, lane = tid & 31;
    const int warp_m = wid & 3;
    const int warp_n = wid >> 2;
    const int bm = blockIdx.y * 128;
    const int bn = blockIdx.x * 128;

    // ---- load A (128 x 256 fp16) once, coalesced ----
    {
        const uint4* src = (const uint4*)(xh + (size_t)bm * D_IN);
        #pragma unroll
        for (int t = 0; t < 16; ++t) {
            int slot = t * 256 + tid;
            int row = slot >> 5;
            int c8  = slot & 31;
            *(uint4*)(smem + row * (KSA * 2) + c8 * 16) = src[slot];
        }
    }

    const int brow = tid >> 1;
    const int bcol = (tid & 1) * 16;

    uint4 rh[2], rl[2];
    auto load_B_regs = [&](int kc) {
        const size_t wb = (size_t)(bn + brow) * D_IN + kc + bcol;
        rh[0] = *(const uint4*)(Wxh + wb);
        rh[1] = *(const uint4*)(Wxh + wb + 8);
        rl[0] = *(const uint4*)(Wxl + wb);
        rl[1] = *(const uint4*)(Wxl + wb + 8);
    };
    auto sts_B = [&]() {
        char* bh = smem + B_OFF;
        char* bl = bh + B_TILE;
        #pragma unroll
        for (int j = 0; j < 2; ++j) {
            unsigned boff = (unsigned)((brow * KSB + bcol + j * 8) * 2);
            *(uint4*)(bh + boff) = rh[j];
            *(uint4*)(bl + boff) = rl[j];
        }
    };

    float acc[2][8][4];
    #pragma unroll
    for (int m = 0; m < 2; ++m)
        #pragma unroll
        for (int n = 0; n < 8; ++n)
            #pragma unroll
            for (int q = 0; q < 4; ++q) acc[m][n][q] = 0.f;

    auto mma_stage = [&](int kc) {
        unsigned bbase = sb + B_OFF;
        #pragma unroll
        for (int ks = 0; ks < 2; ++ks) {
            const int kk = ks * 16 + (lane >> 4) * 8;
            unsigned ah[2][4];
            #pragma unroll
            for (int m = 0; m < 2; ++m) {
                int row = warp_m * 32 + m * 16 + (lane & 15);
                unsigned off = (unsigned)((row * KSA + kc + kk) * 2);
                ldsm_x4(ah[m], sb + off);
            }
            #pragma unroll
            for (int g = 0; g < 4; ++g) {
                int nrow = warp_n * 64 + g * 16 + (lane & 15);
                unsigned off = (unsigned)((nrow * KSB + kk) * 2);
                unsigned bhf[4], blf[4];
                ldsm_x4(bhf, bbase + off);
                ldsm_x4(blf, bbase + B_TILE + off);
                #pragma unroll
                for (int m = 0; m < 2; ++m) {
                    #pragma unroll
                    for (int s = 0; s < 2; ++s) {
                        float* a = acc[m][g * 2 + s];
                        mma_fp16(a, ah[m], bhf[s], bhf[s + 2]);
                        mma_fp16(a, ah[m], blf[s], blf[s + 2]);
                    }
                }
            }
        }
    };

    load_B_regs(0);
    sts_B();
    __syncthreads();

    #pragma unroll 1
    for (int c = 0; c < 8; ++c) {
        if (c < 7) load_B_regs((c + 1) * KCH);   // LDG issues before MMA
        mma_stage(c * KCH);
        if (c < 7) {
            __syncthreads();                     // all warps done reading B
            sts_B();
            __syncthreads();                     // B chunk c+1 ready
        }
    }

    // ---- main epilogue: bias + tanh + store ----
    const int gr = lane >> 2;
    const int gc = (lane & 3) * 2;
    #pragma unroll
    for (int m = 0; m < 2; ++m) {
        #pragma unroll
        for (int n = 0; n < 8; ++n) {
            int col = bn + warp_n * 64 + n * 8 + gc;
            float2 bv = *(const float2*)(g_beff + col);
            int r0 = bm + warp_m * 32 + m * 16 + gr;
            float2 o0, o1;
            o0.x = tanh_fast(acc[m][n][0] + bv.x);
            o0.y = tanh_fast(acc[m][n][1] + bv.y);
            o1.x = tanh_fast(acc[m][n][2] + bv.x);
            o1.y = tanh_fast(acc[m][n][3] + bv.y);
            *(float2*)(out_main + (size_t)r0 * D_IN + col)       = o0;
            *(float2*)(out_main + (size_t)(r0 + 8) * D_IN + col) = o1;
        }
    }

    // ---- raw_feats epilogue, BALANCED across bn CTAs ----
    // bn==0 handles rows [0,64), bn==1 rows [64,128) of this bm tile.
    // 64 rows x 64 float4/row = 4096 positions, 16 iters.
    {
        const int row_base = bm + blockIdx.x * 64;
        #pragma unroll 8
        for (int j = 0; j < 16; ++j) {
            int pos = j * 256 + tid;
            int row = pos >> 6;
            int c4  = pos & 63;
            float4 v = *(const float4*)(x + (size_t)(row_base + row) * D_IN + c4 * 4);
            float4 sc = *(const float4*)(g_scale + c4 * 4);
            float4 sh = *(const float4*)(g_shift + c4 * 4);
            float4 o;
            o.x = tanh_fast(fmaf(v.x, sc.x, sh.x));
            o.y = tanh_fast(fmaf(v.y, sc.y, sh.y));
            o.z = tanh_fast(fmaf(v.z, sc.z, sh.z));
            o.w = tanh_fast(fmaf(v.w, sc.w, sh.w));
            *(float4*)(raw_out + (size_t)(row_base + row) * D_IN + c4 * 4) = o;
        }
    }
}

// ======================= launch ============================================
extern "C" void kernel_launch(void* const* d_in, const int* in_sizes, int n_in,
                              void* d_out, int out_size) {
    const float* x     = (const float*)d_in[0];
    const float* gamma = (const float*)d_in[1];
    const float* beta  = (const float*)d_in[2];
    const float* W1    = (const float*)d_in[3];
    const float* b1    = (const float*)d_in[4];
    const float* W2    = (const float*)d_in[5];
    const float* b2    = (const float*)d_in[6];
    const float* Wf    = (const float*)d_in[7];
    const float* bf    = (const float*)d_in[8];

    float* out_main = (float*)d_out;
    float* out_raw  = (float*)d_out + (size_t)N_ROWS * D_IN;

    float *part0, *T0, *part1;
    __half *Wxh, *Wxl, *xh;
    cudaGetSymbolAddress((void**)&part0, g_part0);
    cudaGetSymbolAddress((void**)&T0,    g_T0);
    cudaGetSymbolAddress((void**)&part1, g_part1);
    cudaGetSymbolAddress((void**)&Wxh,   g_Wxh);
    cudaGetSymbolAddress((void**)&Wxl,   g_Wxl);
    cudaGetSymbolAddress((void**)&xh,    g_xh);

    static cudaStream_t sBN = nullptr;
    static cudaEvent_t evFork = nullptr, evBN = nullptr;
    static int init_done = 0;
    if (!init_done) {
        cudaFuncSetAttribute(fused_main, cudaFuncAttributeMaxDynamicSharedMemorySize,
                             SMEM_MAIN);
        cudaStreamCreateWithFlags(&sBN, cudaStreamNonBlocking);
        cudaEventCreateWithFlags(&evFork, cudaEventDisableTiming);
        cudaEventCreateWithFlags(&evBN,   cudaEventDisableTiming);
        init_done = 1;
    }

    // fork
    cudaEventRecord(evFork, 0);
    cudaStreamWaitEvent(sBN, evFork, 0);

    // BN branch (stream sBN): fused reduce+convert, finalize
    bn_reduce_conv<<<256, 256, 0, sBN>>>(x, xh);
    bn_finalize<<<1, 256, 0, sBN>>>(gamma, beta);
    cudaEventRecord(evBN, sBN);

    // weight collapse branch (default stream)
    gemm_nn_split<<<dim3(512 / 64, 256 / 64, 16), 256>>>(Wf, W2, part0, 256, 512, 2048, 128);
    reduce_splits<<<(256 * 512) / 256, 256>>>(part0, T0, 256 * 512, 16);
    gemm_nn_split<<<dim3(256 / 64, 256 / 64, 16), 256>>>(T0, W1, part1, 256, 256, 512, 32);

    // join
    cudaStreamWaitEvent(0, evBN, 0);

    // fold weights + full bias
    fold_bn<<<256, 256>>>(Wf, b1, b2, bf);

    // fused main
    fused_main<<<dim3(2, N_ROWS / 128), 256, SMEM_MAIN>>>(xh, x, Wxh, Wxl,
                                                          out_main, out_raw);
}

// round 15
// speedup vs baseline: 1.3616x; 1.0943x over previous
#include <cuda_runtime.h>
#include <cuda_bf16.h>
#include <cuda_fp16.h>
#include <math.h>

#define N_ROWS 65536
#define D_IN   256
#define F1     512
#define F2     2048
#define EPS    1e-5f

// ======================= scratch (device globals) ===========================
__device__ float g_bnpart[2 * 256 * 256];
__device__ __align__(16) float g_scale[D_IN];
__device__ __align__(16) float g_shift[D_IN];
__device__ float g_part0[16 * 256 * 512];      // splits of T0 = Wf@W2
__device__ float g_T0[256 * 512];
__device__ float g_part1[16 * 256 * 256];      // splits of Weff = T0@W1
__device__ __align__(16) __half g_Wxh[256 * 256];
__device__ __align__(16) __half g_Wxl[256 * 256];
__device__ __align__(16) __half g_xh[(size_t)N_ROWS * D_IN];   // x as fp16
__device__ __align__(16) float g_beff[D_IN];

__device__ __forceinline__ float tanh_fast(float v) {
    float r;
    asm("tanh.approx.f32 %0, %1;" : "=f"(r) : "f"(v));
    return r;
}

// ============ fused BN reduce + x->fp16 convert (x read ONCE) ==============
__global__ void bn_reduce_conv(const float* __restrict__ x,
                               __half* __restrict__ xh) {
    __shared__ float redS[4][256];
    __shared__ float redQ[4][256];
    const int t = threadIdx.x;
    const int q  = t & 63;
    const int rg = t >> 6;
    const size_t base_row = (size_t)blockIdx.x * 256;

    float s0 = 0.f, s1 = 0.f, s2 = 0.f, s3 = 0.f;
    float q0 = 0.f, q1 = 0.f, q2 = 0.f, q3 = 0.f;
    #pragma unroll 4
    for (int i = 0; i < 64; ++i) {
        const size_t row = base_row + i * 4 + rg;
        float4 v = *(const float4*)(x + row * D_IN + q * 4);
        s0 += v.x; s1 += v.y; s2 += v.z; s3 += v.w;
        q0 += v.x * v.x; q1 += v.y * v.y; q2 += v.z * v.z; q3 += v.w * v.w;
        __half2 h0 = __floats2half2_rn(v.x, v.y);
        __half2 h1 = __floats2half2_rn(v.z, v.w);
        uint2 pk;
        pk.x = *(unsigned*)&h0; pk.y = *(unsigned*)&h1;
        *(uint2*)(xh + row * D_IN + q * 4) = pk;
    }
    redS[rg][q * 4 + 0] = s0; redS[rg][q * 4 + 1] = s1;
    redS[rg][q * 4 + 2] = s2; redS[rg][q * 4 + 3] = s3;
    redQ[rg][q * 4 + 0] = q0; redQ[rg][q * 4 + 1] = q1;
    redQ[rg][q * 4 + 2] = q2; redQ[rg][q * 4 + 3] = q3;
    __syncthreads();
    if (rg == 0) {
        #pragma unroll
        for (int j = 0; j < 4; ++j) {
            int c = q * 4 + j;
            float s  = redS[0][c] + redS[1][c] + redS[2][c] + redS[3][c];
            float sq = redQ[0][c] + redQ[1][c] + redQ[2][c] + redQ[3][c];
            g_bnpart[blockIdx.x * 256 + c]         = s;
            g_bnpart[65536 + blockIdx.x * 256 + c] = sq;
        }
    }
}

__global__ void bn_finalize(const float* __restrict__ gamma,
                            const float* __restrict__ beta) {
    int j = threadIdx.x;
    float s = 0.f, sq = 0.f;
    #pragma unroll 4
    for (int b = 0; b < 256; ++b) {
        s  += g_bnpart[b * 256 + j];
        sq += g_bnpart[65536 + b * 256 + j];
    }
    float inv_n = 1.0f / (float)N_ROWS;
    float mu  = s * inv_n;
    float var = sq * inv_n - mu * mu;
    float sc  = gamma[j] * rsqrtf(var + EPS);
    g_scale[j] = sc;
    g_shift[j] = beta[j] - mu * sc;
}

// ======================= collapse chain ====================================
__global__ void gemm_nn_split(const float* __restrict__ A,
                              const float* __restrict__ B,
                              float* __restrict__ P,
                              int M, int N, int K, int kchunk) {
    __shared__ float As[16][64];
    __shared__ float Bs[16][65];
    const int tid = threadIdx.x;
    const int tx = tid & 15, ty = tid >> 4;
    const int bn = blockIdx.x * 64, bm = blockIdx.y * 64;
    const int k0 = blockIdx.z * kchunk;

    float acc[4][4];
    #pragma unroll
    for (int i = 0; i < 4; ++i)
        #pragma unroll
        for (int j = 0; j < 4; ++j) acc[i][j] = 0.f;

    for (int kb = k0; kb < k0 + kchunk; kb += 16) {
        #pragma unroll
        for (int t = 0; t < 4; ++t) {
            int idx = tid * 4 + t;
            int r = idx >> 4, kk = idx & 15;
            As[kk][r] = A[(size_t)(bm + r) * K + kb + kk];
        }
        #pragma unroll
        for (int t = 0; t < 4; ++t) {
            int idx = tid + t * 256;
            int c = idx & 63, kk = idx >> 6;
            Bs[kk][c] = B[(size_t)(kb + kk) * N + bn + c];
        }
        __syncthreads();
        #pragma unroll
        for (int kk = 0; kk < 16; ++kk) {
            float a[4], b[4];
            #pragma unroll
            for (int i = 0; i < 4; ++i) a[i] = As[kk][ty * 4 + i];
            #pragma unroll
            for (int j = 0; j < 4; ++j) b[j] = Bs[kk][tx * 4 + j];
            #pragma unroll
            for (int i = 0; i < 4; ++i)
                #pragma unroll
                for (int j = 0; j < 4; ++j)
                    acc[i][j] = fmaf(a[i], b[j], acc[i][j]);
        }
        __syncthreads();
    }
    float* Pb = P + (size_t)blockIdx.z * M * N;
    #pragma unroll
    for (int i = 0; i < 4; ++i)
        #pragma unroll
        for (int j = 0; j < 4; ++j)
            Pb[(size_t)(bm + ty * 4 + i) * N + bn + tx * 4 + j] = acc[i][j];
}

__global__ void reduce_splits(const float* __restrict__ P, float* __restrict__ C,
                              int MN, int S) {
    int i = blockIdx.x * 256 + threadIdx.x;
    if (i >= MN) return;
    float s = 0.f;
    for (int k = 0; k < S; ++k) s += P[(size_t)k * MN + i];
    C[i] = s;
}

// fold_bn: Weff row = sum part1; Wx -> fp16 hi/lo;
// beff[i] = Weff[i]@shift + T0[i]@b1 + Wf[i]@b2 + bf[i]
__global__ void fold_bn(const float* __restrict__ Wf,
                        const float* __restrict__ b1,
                        const float* __restrict__ b2,
                        const float* __restrict__ bf) {
    int i = blockIdx.x;
    int t = threadIdx.x;
    float w = 0.f;
    #pragma unroll 4
    for (int s = 0; s < 16; ++s)
        w += g_part1[s * 65536 + i * D_IN + t];
    float wx = w * g_scale[t];
    __half hi = __float2half_rn(wx);
    float lo = wx - __half2float(hi);
    g_Wxh[i * D_IN + t] = hi;
    g_Wxl[i * D_IN + t] = __float2half_rn(lo);

    float r = w * g_shift[t];
    #pragma unroll
    for (int j = 0; j < 2; ++j) {
        int k = t + j * 256;
        r = fmaf(g_T0[i * F1 + k], b1[k], r);
    }
    #pragma unroll
    for (int j = 0; j < 8; ++j) {
        int k = t + j * 256;
        r = fmaf(Wf[(size_t)i * F2 + k], b2[k], r);
    }
    __shared__ float red[256];
    red[t] = r;
    __syncthreads();
    for (int o = 128; o > 0; o >>= 1) {
        if (t < o) red[t] += red[t + o];
        __syncthreads();
    }
    if (t == 0) g_beff[i] = red[0] + bf[i];
}

// ======================= fused HMMA main GEMM (fp16 x2) ====================
// A resident; B double-buffered via cp.async, ONE barrier per chunk.
#define KCH 32
#define KSA 264
#define A_BYTES (128 * KSA * 2)            // 67584
#define KSB 40
#define B_TILE (128 * KSB * 2)             // 10240
#define B_OFF A_BYTES
#define SMEM_MAIN (A_BYTES + 4 * B_TILE)   // 108544 -> 2 CTAs/SM (217KB/227KB)

__device__ __forceinline__ unsigned smem_u32(const void* p) {
    unsigned a;
    asm("{ .reg .u64 t; cvta.to.shared.u64 t, %1; cvt.u32.u64 %0, t; }"
        : "=r"(a) : "l"(p));
    return a;
}

#define CP_ASYNC16(sa, gp) \
    asm volatile("cp.async.cg.shared.global [%0], [%1], 16;" \
        :: "r"(sa), "l"(gp) : "memory")
#define CP_COMMIT() asm volatile("cp.async.commit_group;" ::: "memory")
#define CP_WAIT0()  asm volatile("cp.async.wait_group 0;" ::: "memory")

__device__ __forceinline__ void ldsm_x4(unsigned r[4], unsigned addr) {
    asm volatile("ldmatrix.sync.aligned.m8n8.x4.shared.b16 {%0,%1,%2,%3}, [%4];"
                 : "=r"(r[0]), "=r"(r[1]), "=r"(r[2]), "=r"(r[3]) : "r"(addr));
}

__device__ __forceinline__ void mma_fp16(float c[4], const unsigned a[4],
                                         unsigned b0, unsigned b1) {
    asm volatile(
        "mma.sync.aligned.m16n8k16.row.col.f32.f16.f16.f32 "
        "{%0,%1,%2,%3}, {%4,%5,%6,%7}, {%8,%9}, {%0,%1,%2,%3};"
        : "+f"(c[0]), "+f"(c[1]), "+f"(c[2]), "+f"(c[3])
        : "r"(a[0]), "r"(a[1]), "r"(a[2]), "r"(a[3]), "r"(b0), "r"(b1));
}

__global__ __launch_bounds__(256, 2)
void fused_main(const __half* __restrict__ xh,
                const float* __restrict__ x,
                const __half* __restrict__ Wxh,
                const __half* __restrict__ Wxl,
                float* __restrict__ out_main,
                float* __restrict__ raw_out) {
    extern __shared__ __align__(16) char smem[];
    const unsigned sb = smem_u32(smem);
    const int tid = threadIdx.x;
    const int wid = tid >> 5, lane = tid & 31;
    const int warp_m = wid & 3;
    const int warp_n = wid >> 2;
    const int bm = blockIdx.y * 128;
    const int bn = blockIdx.x * 128;

    const int brow = tid >> 1;
    const int bcol = (tid & 1) * 16;

    // issue cp.async for B chunk kc into stage
    auto cp_B = [&](int kc, int stage) {
        const size_t wb = (size_t)(bn + brow) * D_IN + kc + bcol;
        unsigned bh = sb + B_OFF + stage * 2 * B_TILE;
        unsigned bl = bh + B_TILE;
        #pragma unroll
        for (int j = 0; j < 2; ++j) {
            unsigned boff = (unsigned)((brow * KSB + bcol + j * 8) * 2);
            CP_ASYNC16(bh + boff, (const void*)(Wxh + wb + j * 8));
            CP_ASYNC16(bl + boff, (const void*)(Wxl + wb + j * 8));
        }
    };

    // ---- prologue: cp.async A (whole tile) + B chunk0, one group ----
    {
        const char* srcA = (const char*)(xh + (size_t)bm * D_IN);
        #pragma unroll
        for (int t = 0; t < 16; ++t) {
            int slot = t * 256 + tid;
            int row = slot >> 5;
            int c8  = slot & 31;
            CP_ASYNC16(sb + row * (KSA * 2) + c8 * 16, srcA + slot * 16);
        }
        cp_B(0, 0);
        CP_COMMIT();
    }

    float acc[2][8][4];
    #pragma unroll
    for (int m = 0; m < 2; ++m)
        #pragma unroll
        for (int n = 0; n < 8; ++n)
            #pragma unroll
            for (int q = 0; q < 4; ++q) acc[m][n][q] = 0.f;

    auto mma_stage = [&](int kc, int stage) {
        unsigned bbase = sb + B_OFF + stage * 2 * B_TILE;
        #pragma unroll
        for (int ks = 0; ks < 2; ++ks) {
            const int kk = ks * 16 + (lane >> 4) * 8;
            unsigned ah[2][4];
            #pragma unroll
            for (int m = 0; m < 2; ++m) {
                int row = warp_m * 32 + m * 16 + (lane & 15);
                unsigned off = (unsigned)((row * KSA + kc + kk) * 2);
                ldsm_x4(ah[m], sb + off);
            }
            #pragma unroll
            for (int g = 0; g < 4; ++g) {
                int nrow = warp_n * 64 + g * 16 + (lane & 15);
                unsigned off = (unsigned)((nrow * KSB + kk) * 2);
                unsigned bhf[4], blf[4];
                ldsm_x4(bhf, bbase + off);
                ldsm_x4(blf, bbase + B_TILE + off);
                #pragma unroll
                for (int m = 0; m < 2; ++m) {
                    #pragma unroll
                    for (int s = 0; s < 2; ++s) {
                        float* a = acc[m][g * 2 + s];
                        mma_fp16(a, ah[m], bhf[s], bhf[s + 2]);
                        mma_fp16(a, ah[m], blf[s], blf[s + 2]);
                    }
                }
            }
        }
    };

    CP_WAIT0();
    __syncthreads();

    // ---- mainloop: issue next-chunk copy, mma current, wait+sync ----
    #pragma unroll 1
    for (int c = 0; c < 8; ++c) {
        if (c < 7) {
            cp_B((c + 1) * KCH, (c + 1) & 1);
            CP_COMMIT();
        }
        mma_stage(c * KCH, c & 1);
        if (c < 7) {
            CP_WAIT0();
            __syncthreads();
        }
    }

    // ---- main epilogue: bias + tanh + store ----
    const int gr = lane >> 2;
    const int gc = (lane & 3) * 2;
    #pragma unroll
    for (int m = 0; m < 2; ++m) {
        #pragma unroll
        for (int n = 0; n < 8; ++n) {
            int col = bn + warp_n * 64 + n * 8 + gc;
            float2 bv = *(const float2*)(g_beff + col);
            int r0 = bm + warp_m * 32 + m * 16 + gr;
            float2 o0, o1;
            o0.x = tanh_fast(acc[m][n][0] + bv.x);
            o0.y = tanh_fast(acc[m][n][1] + bv.y);
            o1.x = tanh_fast(acc[m][n][2] + bv.x);
            o1.y = tanh_fast(acc[m][n][3] + bv.y);
            *(float2*)(out_main + (size_t)r0 * D_IN + col)       = o0;
            *(float2*)(out_main + (size_t)(r0 + 8) * D_IN + col) = o1;
        }
    }

    // ---- raw_feats epilogue, balanced: bn CTA handles 64 rows ----
    {
        const int row_base = bm + blockIdx.x * 64;
        #pragma unroll 8
        for (int j = 0; j < 16; ++j) {
            int pos = j * 256 + tid;
            int row = pos >> 6;
            int c4  = pos & 63;
            float4 v = *(const float4*)(x + (size_t)(row_base + row) * D_IN + c4 * 4);
            float4 sc = *(const float4*)(g_scale + c4 * 4);
            float4 sh = *(const float4*)(g_shift + c4 * 4);
            float4 o;
            o.x = tanh_fast(fmaf(v.x, sc.x, sh.x));
            o.y = tanh_fast(fmaf(v.y, sc.y, sh.y));
            o.z = tanh_fast(fmaf(v.z, sc.z, sh.z));
            o.w = tanh_fast(fmaf(v.w, sc.w, sh.w));
            *(float4*)(raw_out + (size_t)(row_base + row) * D_IN + c4 * 4) = o;
        }
    }
}

// ======================= launch ============================================
extern "C" void kernel_launch(void* const* d_in, const int* in_sizes, int n_in,
                              void* d_out, int out_size) {
    const float* x     = (const float*)d_in[0];
    const float* gamma = (const float*)d_in[1];
    const float* beta  = (const float*)d_in[2];
    const float* W1    = (const float*)d_in[3];
    const float* b1    = (const float*)d_in[4];
    const float* W2    = (const float*)d_in[5];
    const float* b2    = (const float*)d_in[6];
    const float* Wf    = (const float*)d_in[7];
    const float* bf    = (const float*)d_in[8];

    float* out_main = (float*)d_out;
    float* out_raw  = (float*)d_out + (size_t)N_ROWS * D_IN;

    float *part0, *T0, *part1;
    __half *Wxh, *Wxl, *xh;
    cudaGetSymbolAddress((void**)&part0, g_part0);
    cudaGetSymbolAddress((void**)&T0,    g_T0);
    cudaGetSymbolAddress((void**)&part1, g_part1);
    cudaGetSymbolAddress((void**)&Wxh,   g_Wxh);
    cudaGetSymbolAddress((void**)&Wxl,   g_Wxl);
    cudaGetSymbolAddress((void**)&xh,    g_xh);

    static cudaStream_t sBN = nullptr;
    static cudaEvent_t evFork = nullptr, evBN = nullptr;
    static int init_done = 0;
    if (!init_done) {
        cudaFuncSetAttribute(fused_main, cudaFuncAttributeMaxDynamicSharedMemorySize,
                             SMEM_MAIN);
        cudaStreamCreateWithFlags(&sBN, cudaStreamNonBlocking);
        cudaEventCreateWithFlags(&evFork, cudaEventDisableTiming);
        cudaEventCreateWithFlags(&evBN,   cudaEventDisableTiming);
        init_done = 1;
    }

    // fork
    cudaEventRecord(evFork, 0);
    cudaStreamWaitEvent(sBN, evFork, 0);

    // BN branch (stream sBN): fused reduce+convert, finalize
    bn_reduce_conv<<<256, 256, 0, sBN>>>(x, xh);
    bn_finalize<<<1, 256, 0, sBN>>>(gamma, beta);
    cudaEventRecord(evBN, sBN);

    // weight collapse branch (default stream)
    gemm_nn_split<<<dim3(512 / 64, 256 / 64, 16), 256>>>(Wf, W2, part0, 256, 512, 2048, 128);
    reduce_splits<<<(256 * 512) / 256, 256>>>(part0, T0, 256 * 512, 16);
    gemm_nn_split<<<dim3(256 / 64, 256 / 64, 16), 256>>>(T0, W1, part1, 256, 256, 512, 32);

    // join
    cudaStreamWaitEvent(0, evBN, 0);

    // fold weights + full bias
    fold_bn<<<256, 256>>>(Wf, b1, b2, bf);

    // fused main
    fused_main<<<dim3(2, N_ROWS / 128), 256, SMEM_MAIN>>>(xh, x, Wxh, Wxl,
                                                          out_main, out_raw);
}